// round 3
// baseline (speedup 1.0000x reference)
#include <cuda_runtime.h>

// SpikeLayer LIF scan: x [B=64, T=8, C=256, H=32, W=32] f32 -> spikes, same shape.
// mem = mem*0.25 + x; spike = (mem - 0.5) > 0; mem = (1-spike)*mem.
//
// Persistent grid-stride version: exactly one wave of CTAs stays resident and
// loops over chunks, removing ~21 wave transitions and pipelining the
// front-batched-load CTA spread. One thread owns 4 neurons (float4) across all
// 8 timesteps; recurrence lives in registers. All indexing 32-bit (tensor is
// 2^25 float4 vectors).

#define LIF_T 8
#define VTH 0.5f
#define DECAY 0.25f
#define CHW4 65536u                 // C*H*W/4 float4 per (b,t) slice
#define NCHUNK (CHW4 * 8u)          // float4 per batch sample (T*CHW4)

__global__ __launch_bounds__(256) void lif_scan_kernel(
    const float4* __restrict__ x, float4* __restrict__ out,
    unsigned total_n)               // total neurons/4 = B * CHW4
{
    const unsigned stride = gridDim.x * 256u;

    for (unsigned i = blockIdx.x * 256u + threadIdx.x; i < total_n; i += stride) {
        // b = i / CHW4, n = i % CHW4  (CHW4 = 2^16: shifts, no div)
        unsigned b = i >> 16;
        unsigned n = i & (CHW4 - 1u);
        unsigned base = b * NCHUNK + n;

        float4 v[LIF_T];
        // Front-batched independent loads: MLP = 8 LDG.128
        #pragma unroll
        for (int t = 0; t < LIF_T; t++)
            v[t] = x[base + (unsigned)t * CHW4];

        float mx = 0.f, my = 0.f, mz = 0.f, mw = 0.f;
        #pragma unroll
        for (int t = 0; t < LIF_T; t++) {
            mx = fmaf(mx, DECAY, v[t].x);
            my = fmaf(my, DECAY, v[t].y);
            mz = fmaf(mz, DECAY, v[t].z);
            mw = fmaf(mw, DECAY, v[t].w);
            float sx = (mx > VTH) ? 1.f : 0.f;
            float sy = (my > VTH) ? 1.f : 0.f;
            float sz = (mz > VTH) ? 1.f : 0.f;
            float sw = (mw > VTH) ? 1.f : 0.f;
            // hard reset where spiked
            mx = (sx != 0.f) ? 0.f : mx;
            my = (sy != 0.f) ? 0.f : my;
            mz = (sz != 0.f) ? 0.f : mz;
            mw = (sw != 0.f) ? 0.f : mw;
            v[t].x = sx; v[t].y = sy; v[t].z = sz; v[t].w = sw;
        }

        #pragma unroll
        for (int t = 0; t < LIF_T; t++)
            out[base + (unsigned)t * CHW4] = v[t];
    }
}

extern "C" void kernel_launch(void* const* d_in, const int* in_sizes, int n_in,
                              void* d_out, int out_size)
{
    const float4* x = (const float4*)d_in[0];
    float4* out = (float4*)d_out;

    unsigned total   = (unsigned)in_sizes[0];      // B*T*C*H*W elements
    unsigned total_n = total / (4u * LIF_T);       // float4 vectors per timestep

    // One resident wave: 148 SMs x ~5 CTAs (256 thr, ~40 regs) -> 740;
    // use a small multiple for load balance without re-introducing many waves.
    unsigned blocks = 148u * 5u * 2u;              // 1480 CTAs, ~11 chunks each
    unsigned needed = (total_n + 255u) / 256u;
    if (blocks > needed) blocks = needed;

    lif_scan_kernel<<<blocks, 256>>>(x, out, total_n);
}

// round 4
// speedup vs baseline: 1.0782x; 1.0782x over previous
#include <cuda_runtime.h>

// SpikeLayer LIF scan: x [B=64, T=8, C=256, H=32, W=32] f32 -> spikes, same shape.
// mem = mem*0.25 + x; spike = (mem - 0.5) > 0; mem = (1-spike)*mem.
//
// R1 structure (best: 150us kernel): flat one-shot grid, one thread = 4 neurons
// (float4) across all 8 timesteps, recurrence in registers, front-batched
// MLP=8 loads, default cache ops. R4 micro-fixes: 2D grid (y=batch) removes the
// 64-bit div; all index math 32-bit.

#define LIF_T 8
#define VTH 0.5f
#define DECAY 0.25f
#define CHW4 65536u                  // C*H*W/4 float4 vectors per (b,t) slice
#define BSTRIDE (CHW4 * 8u)          // float4 vectors per batch sample

__global__ __launch_bounds__(256) void lif_scan_kernel(
    const float4* __restrict__ x, float4* __restrict__ out)
{
    unsigned n    = blockIdx.x * 256u + threadIdx.x;   // [0, CHW4)
    unsigned base = blockIdx.y * BSTRIDE + n;

    float4 v[LIF_T];
    // Front-batched independent loads: MLP = 8 LDG.128
    #pragma unroll
    for (int t = 0; t < LIF_T; t++)
        v[t] = x[base + (unsigned)t * CHW4];

    float mx = 0.f, my = 0.f, mz = 0.f, mw = 0.f;
    #pragma unroll
    for (int t = 0; t < LIF_T; t++) {
        mx = fmaf(mx, DECAY, v[t].x);
        my = fmaf(my, DECAY, v[t].y);
        mz = fmaf(mz, DECAY, v[t].z);
        mw = fmaf(mw, DECAY, v[t].w);
        float sx = (mx > VTH) ? 1.f : 0.f;
        float sy = (my > VTH) ? 1.f : 0.f;
        float sz = (mz > VTH) ? 1.f : 0.f;
        float sw = (mw > VTH) ? 1.f : 0.f;
        // hard reset where spiked
        mx = (sx != 0.f) ? 0.f : mx;
        my = (sy != 0.f) ? 0.f : my;
        mz = (sz != 0.f) ? 0.f : mz;
        mw = (sw != 0.f) ? 0.f : mw;
        v[t].x = sx; v[t].y = sy; v[t].z = sz; v[t].w = sw;
    }

    #pragma unroll
    for (int t = 0; t < LIF_T; t++)
        out[base + (unsigned)t * CHW4] = v[t];
}

extern "C" void kernel_launch(void* const* d_in, const int* in_sizes, int n_in,
                              void* d_out, int out_size)
{
    const float4* x = (const float4*)d_in[0];
    float4* out = (float4*)d_out;

    unsigned total   = (unsigned)in_sizes[0];          // B*T*C*H*W
    unsigned batches = total / (LIF_T * CHW4 * 4u);    // = 64 for bench shape

    dim3 grid(CHW4 / 256u, batches, 1);                // (256, 64) = 16384 CTAs
    lif_scan_kernel<<<grid, 256>>>(x, out);
}